// round 2
// baseline (speedup 1.0000x reference)
#include <cuda_runtime.h>
#include <cuda_bf16.h>
#include <math.h>

// ---------------------------------------------------------------------------
// FixedEmbedderNN — algebraically collapsed:
//   z0 = sum_f T[f][code_f] + sum_f v_f * P[f] + c0        (pre-LN layer0)
//   zn0 = LNnorm(z0);  z1 = zn0 @ M1 + c1;  zn1 = LNnorm(z1)
//   out = zn1 @ Mo + co
// where T,P fold (emb/W_num) @ W_in @ W1[0] @ W2[0]; M1 = diag(g0) W1[1] W2[1];
// Mo = diag(g1) W_out; biases folded accordingly.
// ---------------------------------------------------------------------------

#define NCAT 20
#define NNUM 20
#define HID 128
#define LN_EPS 1e-5f

// scratch (device globals; no allocations allowed)
__device__ float g_A[1280 * 256];     // W_in @ W1[0]
__device__ float g_Wfold[1280 * 128]; // (W_in @ W1[0]) @ W2[0]
__device__ float g_B1[128 * 128];     // W1[1] @ W2[1]
__device__ float g_T[NCAT * 50 * 128];
__device__ float g_P[NNUM * 128];
__device__ float g_M1[128 * 128];
__device__ float g_Mo[128 * 128];
__device__ float g_c0[128];
__device__ float g_c1[128];
__device__ float g_co[128];

// ------------------------- generic tiled SGEMM (precompute only) -----------
__global__ void sgemm32(const float* __restrict__ A, const float* __restrict__ B,
                        float* __restrict__ C, int M, int N, int K) {
    __shared__ float As[32][33];
    __shared__ float Bs[32][33];
    int bx = blockIdx.x * 32;  // row tile
    int by = blockIdx.y * 32;  // col tile
    int tx = threadIdx.x & 31;
    int ty = threadIdx.x >> 5;  // 0..7
    float acc[4] = {0.f, 0.f, 0.f, 0.f};
    for (int k0 = 0; k0 < K; k0 += 32) {
        #pragma unroll
        for (int i = 0; i < 4; i++) {
            As[ty + 8 * i][tx] = A[(size_t)(bx + ty + 8 * i) * K + k0 + tx];
            Bs[ty + 8 * i][tx] = B[(size_t)(k0 + ty + 8 * i) * N + by + tx];
        }
        __syncthreads();
        #pragma unroll
        for (int kk = 0; kk < 32; kk++) {
            float b = Bs[kk][tx];
            #pragma unroll
            for (int i = 0; i < 4; i++) acc[i] += As[ty + 8 * i][kk] * b;
        }
        __syncthreads();
    }
    #pragma unroll
    for (int i = 0; i < 4; i++) C[(size_t)(bx + ty + 8 * i) * N + by + tx] = acc[i];
}

// ------------------------- table builders ----------------------------------
__global__ void build_T(const float* __restrict__ emb) {
    int fc = blockIdx.x;           // f*50 + c
    int f = fc / 50;
    int j = threadIdx.x;
    __shared__ float e[32];
    if (j < 32) e[j] = emb[fc * 32 + j];
    __syncthreads();
    float acc = 0.f;
    #pragma unroll
    for (int i = 0; i < 32; i++) acc += e[i] * g_Wfold[(f * 32 + i) * 128 + j];
    g_T[fc * 128 + j] = acc;
}

__global__ void build_P(const float* __restrict__ W_num) {
    int f = blockIdx.x;
    int j = threadIdx.x;
    __shared__ float w[32];
    if (j < 32) w[j] = W_num[f * 32 + j];
    __syncthreads();
    float acc = 0.f;
    #pragma unroll
    for (int i = 0; i < 32; i++) acc += w[i] * g_Wfold[(640 + f * 32 + i) * 128 + j];
    g_P[f * 128 + j] = acc;
}

__global__ void scaleM(const float* __restrict__ ln_g, const float* __restrict__ W_out) {
    int k = blockIdx.x;
    int j = threadIdx.x;
    g_M1[k * 128 + j] = ln_g[k] * g_B1[k * 128 + j];
    g_Mo[k * 128 + j] = ln_g[128 + k] * W_out[k * 128 + j];
}

__global__ void build_biases(const float* __restrict__ b_num, const float* __restrict__ b_in,
                             const float* __restrict__ W1, const float* __restrict__ b1,
                             const float* __restrict__ W2, const float* __restrict__ b2,
                             const float* __restrict__ ln_b, const float* __restrict__ W_out,
                             const float* __restrict__ b_out) {
    __shared__ float u[256];
    int j = threadIdx.x;  // 128 threads
    // u0[m] = b1[0][m] + sum_k b_in[k] * W1[0][k][m]
    for (int m = j; m < 256; m += 128) {
        float s = b1[m];
        for (int k = 0; k < 128; k++) s += b_in[k] * W1[k * 256 + m];
        u[m] = s;
    }
    __syncthreads();
    // c0 = b2[0] + u0 @ W2[0] + b_num_flat @ Wfold[640:]
    float c0 = b2[j];
    for (int m = 0; m < 256; m++) c0 += u[m] * W2[m * 128 + j];
    for (int i = 0; i < 640; i++) c0 += b_num[i] * g_Wfold[(640 + i) * 128 + j];
    g_c0[j] = c0;
    // c1 = b2[1] + ln_b[0] @ B1 + b1[1] @ W2[1]
    float c1 = b2[128 + j];
    for (int k = 0; k < 128; k++) c1 += ln_b[k] * g_B1[k * 128 + j];
    for (int m = 0; m < 256; m++) c1 += b1[256 + m] * W2[(256 + m) * 128 + j];
    g_c1[j] = c1;
    // co = b_out + ln_b[1] @ W_out
    float co = b_out[j];
    for (int k = 0; k < 128; k++) co += ln_b[128 + k] * W_out[k * 128 + j];
    g_co[j] = co;
}

// ------------------------- main fused kernel --------------------------------
#define TROWS 128
#define SP 132  // padded row stride in smem (floats)
#define SMEM_FLOATS (TROWS * SP + TROWS * NCAT /*codes*/ + TROWS * NNUM /*nums*/)
#define SMEM_BYTES (SMEM_FLOATS * 4)

__global__ __launch_bounds__(256, 2) void main_kernel(const float* __restrict__ x,
                                                      float* __restrict__ out, int nrows) {
    extern __shared__ float sm[];
    float* S = sm;                                 // [128][SP]
    int* codes = (int*)(sm + TROWS * SP);          // [128][20]
    float* nums = (float*)(codes + TROWS * NCAT);  // [128][20]

    const int t = threadIdx.x;
    const int rowbase = blockIdx.x * TROWS;

    // ---- load x tile: codes (categorical) + values (numeric) ----
    for (int i = t; i < TROWS * 40; i += 256) {
        int r = i / 40, f = i % 40;
        int gr = rowbase + r;
        float v = (gr < nrows) ? x[(size_t)gr * 40 + f] : 0.f;
        if (f < NCAT) {
            int c = (int)v;
            c = c < 0 ? 0 : (c > 49 ? 49 : c);
            codes[r * NCAT + f] = c;
        } else {
            nums[r * NNUM + (f - NCAT)] = v;
        }
    }
    __syncthreads();

    // ---- gather phase: z0 accumulation in registers ----
    // thread t: j4 = t&31 (cols 4*j4..), warp w = t>>5, rows r = 8*s + w, s<16
    {
        const int j4 = t & 31;
        const int w = t >> 5;
        float4 acc[16];
        float4 cz = *(const float4*)&g_c0[4 * j4];
        #pragma unroll
        for (int s = 0; s < 16; s++) acc[s] = cz;

        for (int f = 0; f < NCAT; f++) {
            float4 pv = *(const float4*)&g_P[f * 128 + 4 * j4];
            const float* Tf = g_T + f * 50 * 128;
            #pragma unroll
            for (int s = 0; s < 16; s++) {
                int r = 8 * s + w;
                int c = codes[r * NCAT + f];
                float v = nums[r * NNUM + f];
                float4 tv = *(const float4*)&Tf[c * 128 + 4 * j4];
                acc[s].x = fmaf(v, pv.x, acc[s].x + tv.x);
                acc[s].y = fmaf(v, pv.y, acc[s].y + tv.y);
                acc[s].z = fmaf(v, pv.z, acc[s].z + tv.z);
                acc[s].w = fmaf(v, pv.w, acc[s].w + tv.w);
            }
        }

        // ---- LN0 (warp-wide: whole row lives in one warp) + store to S ----
        #pragma unroll
        for (int s = 0; s < 16; s++) {
            int r = 8 * s + w;
            float s1 = acc[s].x + acc[s].y + acc[s].z + acc[s].w;
            float s2 = acc[s].x * acc[s].x + acc[s].y * acc[s].y +
                       acc[s].z * acc[s].z + acc[s].w * acc[s].w;
            #pragma unroll
            for (int o = 16; o > 0; o >>= 1) {
                s1 += __shfl_xor_sync(0xffffffffu, s1, o);
                s2 += __shfl_xor_sync(0xffffffffu, s2, o);
            }
            float mu = s1 * (1.f / 128.f);
            float var = s2 * (1.f / 128.f) - mu * mu;
            float inv = rsqrtf(var + LN_EPS);
            float4 zn;
            zn.x = (acc[s].x - mu) * inv;
            zn.y = (acc[s].y - mu) * inv;
            zn.z = (acc[s].z - mu) * inv;
            zn.w = (acc[s].w - mu) * inv;
            *(float4*)&S[r * SP + 4 * j4] = zn;
        }
    }
    __syncthreads();

    // ---- GEMM1: z1 = zn0 @ M1 + c1 (thread: 8 rows x 8 cols) ----
    const int tr = t >> 4;  // 0..15 -> rows 8*tr..+7
    const int tc = t & 15;  // 0..15 -> cols 8*tc..+7
    float z[8][8];
    {
        float4 cb0 = *(const float4*)&g_c1[8 * tc];
        float4 cb1 = *(const float4*)&g_c1[8 * tc + 4];
        #pragma unroll
        for (int i = 0; i < 8; i++) {
            z[i][0] = cb0.x; z[i][1] = cb0.y; z[i][2] = cb0.z; z[i][3] = cb0.w;
            z[i][4] = cb1.x; z[i][5] = cb1.y; z[i][6] = cb1.z; z[i][7] = cb1.w;
        }
        #pragma unroll 4
        for (int k = 0; k < 128; k++) {
            float a[8];
            #pragma unroll
            for (int i = 0; i < 8; i++) a[i] = S[(8 * tr + i) * SP + k];
            float4 b0 = __ldg((const float4*)&g_M1[k * 128 + 8 * tc]);
            float4 b1v = __ldg((const float4*)&g_M1[k * 128 + 8 * tc + 4]);
            #pragma unroll
            for (int i = 0; i < 8; i++) {
                z[i][0] = fmaf(a[i], b0.x, z[i][0]);
                z[i][1] = fmaf(a[i], b0.y, z[i][1]);
                z[i][2] = fmaf(a[i], b0.z, z[i][2]);
                z[i][3] = fmaf(a[i], b0.w, z[i][3]);
                z[i][4] = fmaf(a[i], b1v.x, z[i][4]);
                z[i][5] = fmaf(a[i], b1v.y, z[i][5]);
                z[i][6] = fmaf(a[i], b1v.z, z[i][6]);
                z[i][7] = fmaf(a[i], b1v.w, z[i][7]);
            }
        }
    }

    // ---- LN1: row spread across 16 lanes (same tr); reduce via shfl_xor<=8 ----
    #pragma unroll
    for (int i = 0; i < 8; i++) {
        float s1 = 0.f, s2 = 0.f;
        #pragma unroll
        for (int jj = 0; jj < 8; jj++) { s1 += z[i][jj]; s2 += z[i][jj] * z[i][jj]; }
        #pragma unroll
        for (int o = 8; o > 0; o >>= 1) {
            s1 += __shfl_xor_sync(0xffffffffu, s1, o);
            s2 += __shfl_xor_sync(0xffffffffu, s2, o);
        }
        float mu = s1 * (1.f / 128.f);
        float var = s2 * (1.f / 128.f) - mu * mu;
        float inv = rsqrtf(var + LN_EPS);
        #pragma unroll
        for (int jj = 0; jj < 8; jj++) z[i][jj] = (z[i][jj] - mu) * inv;
    }
    __syncthreads();  // all GEMM1 reads of S complete before overwrite
    #pragma unroll
    for (int i = 0; i < 8; i++) {
        *(float4*)&S[(8 * tr + i) * SP + 8 * tc] = make_float4(z[i][0], z[i][1], z[i][2], z[i][3]);
        *(float4*)&S[(8 * tr + i) * SP + 8 * tc + 4] = make_float4(z[i][4], z[i][5], z[i][6], z[i][7]);
    }
    __syncthreads();

    // ---- GEMM2: out = zn1 @ Mo + co ----
    {
        float4 cb0 = *(const float4*)&g_co[8 * tc];
        float4 cb1 = *(const float4*)&g_co[8 * tc + 4];
        #pragma unroll
        for (int i = 0; i < 8; i++) {
            z[i][0] = cb0.x; z[i][1] = cb0.y; z[i][2] = cb0.z; z[i][3] = cb0.w;
            z[i][4] = cb1.x; z[i][5] = cb1.y; z[i][6] = cb1.z; z[i][7] = cb1.w;
        }
        #pragma unroll 4
        for (int k = 0; k < 128; k++) {
            float a[8];
            #pragma unroll
            for (int i = 0; i < 8; i++) a[i] = S[(8 * tr + i) * SP + k];
            float4 b0 = __ldg((const float4*)&g_Mo[k * 128 + 8 * tc]);
            float4 b1v = __ldg((const float4*)&g_Mo[k * 128 + 8 * tc + 4]);
            #pragma unroll
            for (int i = 0; i < 8; i++) {
                z[i][0] = fmaf(a[i], b0.x, z[i][0]);
                z[i][1] = fmaf(a[i], b0.y, z[i][1]);
                z[i][2] = fmaf(a[i], b0.z, z[i][2]);
                z[i][3] = fmaf(a[i], b0.w, z[i][3]);
                z[i][4] = fmaf(a[i], b1v.x, z[i][4]);
                z[i][5] = fmaf(a[i], b1v.y, z[i][5]);
                z[i][6] = fmaf(a[i], b1v.z, z[i][6]);
                z[i][7] = fmaf(a[i], b1v.w, z[i][7]);
            }
        }
        #pragma unroll
        for (int i = 0; i < 8; i++) {
            int gr = rowbase + 8 * tr + i;
            if (gr < nrows) {
                *(float4*)&out[(size_t)gr * 128 + 8 * tc] =
                    make_float4(z[i][0], z[i][1], z[i][2], z[i][3]);
                *(float4*)&out[(size_t)gr * 128 + 8 * tc + 4] =
                    make_float4(z[i][4], z[i][5], z[i][6], z[i][7]);
            }
        }
    }
}

// ---------------------------------------------------------------------------
extern "C" void kernel_launch(void* const* d_in, const int* in_sizes, int n_in,
                              void* d_out, int out_size) {
    const float* x     = (const float*)d_in[0];
    const float* emb   = (const float*)d_in[1];
    const float* W_num = (const float*)d_in[2];
    const float* b_num = (const float*)d_in[3];
    const float* W_in  = (const float*)d_in[4];
    const float* b_in  = (const float*)d_in[5];
    const float* W1    = (const float*)d_in[6];
    const float* b1    = (const float*)d_in[7];
    const float* W2    = (const float*)d_in[8];
    const float* b2    = (const float*)d_in[9];
    const float* ln_g  = (const float*)d_in[10];
    const float* ln_b  = (const float*)d_in[11];
    const float* W_out = (const float*)d_in[12];
    const float* b_out = (const float*)d_in[13];
    float* out = (float*)d_out;

    int nrows = in_sizes[0] / 40;
    int ntiles = (nrows + TROWS - 1) / TROWS;

    cudaFuncSetAttribute(main_kernel, cudaFuncAttributeMaxDynamicSharedMemorySize, SMEM_BYTES);

    float *pA, *pWfold, *pB1;
    cudaGetSymbolAddress((void**)&pA, g_A);
    cudaGetSymbolAddress((void**)&pWfold, g_Wfold);
    cudaGetSymbolAddress((void**)&pB1, g_B1);

    // precompute chain (graph-ordered on default stream)
    sgemm32<<<dim3(1280 / 32, 256 / 32), 256>>>(W_in, W1, pA, 1280, 256, 128);
    sgemm32<<<dim3(1280 / 32, 128 / 32), 256>>>(pA, W2, pWfold, 1280, 128, 256);
    sgemm32<<<dim3(128 / 32, 128 / 32), 256>>>(W1 + 128 * 256, W2 + 256 * 128, pB1, 128, 128, 256);
    build_T<<<NCAT * 50, 128>>>(emb);
    build_P<<<NNUM, 128>>>(W_num);
    scaleM<<<128, 128>>>(ln_g, W_out);
    build_biases<<<1, 128>>>(b_num, b_in, W1, b1, W2, b2, ln_b, W_out, b_out);

    main_kernel<<<ntiles, 256, SMEM_BYTES>>>(x, out, nrows);
}